// round 2
// baseline (speedup 1.0000x reference)
#include <cuda_runtime.h>
#include <cstdint>

#define B 512
#define DX 128
#define H 512

// Scratch (no allocs allowed): hx[B][H], hyb[B][H] (= hy + b1), W2t[k][n]
__device__ float g_hx[B * H];
__device__ float g_hyb[B * H];
__device__ float g_W2t[H * H];

// ---------------------------------------------------------------------------
// First layer: out[r][h] = sum_d in[r][d] * W1[h][off+d] (+ b1[h] if addb)
// Tiny GEMM (512x512x128) — simple 16x16 smem tiles, fully coalesced.
// ---------------------------------------------------------------------------
__global__ void gemm_h_kernel(const float* __restrict__ in,
                              const float* __restrict__ W1,
                              const float* __restrict__ b1,
                              int off, int addb) {
    __shared__ float xs[16][17];
    __shared__ float ws[16][17];
    int tx = threadIdx.x, ty = threadIdx.y;
    int r0 = blockIdx.y * 16, h0 = blockIdx.x * 16;
    float acc = 0.f;
    for (int kt = 0; kt < DX; kt += 16) {
        xs[ty][tx] = in[(r0 + ty) * DX + kt + tx];
        ws[ty][tx] = W1[(h0 + ty) * (2 * DX) + off + kt + tx];
        __syncthreads();
#pragma unroll
        for (int k = 0; k < 16; k++)
            acc = fmaf(xs[ty][k], ws[tx][k], acc);
        __syncthreads();
    }
    float bv = addb ? b1[h0 + tx] : 0.f;
    float* outp = addb ? g_hyb : g_hx;
    outp[(r0 + ty) * H + h0 + tx] = acc + bv;
}

// ---------------------------------------------------------------------------
// Transpose W2 [n][k] -> W2t [k][n] so the main kernel's smem tile loads are
// coalesced and bank-conflict-free (k-major in smem).
// ---------------------------------------------------------------------------
__global__ void transpose_kernel(const float* __restrict__ W2) {
    __shared__ float s[32][33];
    int tx = threadIdx.x, ty = threadIdx.y;
    int n0 = blockIdx.y * 32, k0 = blockIdx.x * 32;
#pragma unroll
    for (int yy = 0; yy < 32; yy += 8)
        s[ty + yy][tx] = W2[(n0 + ty + yy) * H + k0 + tx];
    __syncthreads();
#pragma unroll
    for (int yy = 0; yy < 32; yy += 8)
        g_W2t[(k0 + ty + yy) * H + n0 + tx] = s[tx][ty + yy];
}

// ---------------------------------------------------------------------------
// f32x2 packed-FMA helpers (FFMA2 — 2 fp32 FMA per issue on sm_103a)
// ---------------------------------------------------------------------------
__device__ __forceinline__ unsigned long long pack2(float v) {
    unsigned long long r;
    unsigned int u = __float_as_uint(v);
    asm("mov.b64 %0, {%1, %1};" : "=l"(r) : "r"(u));
    return r;
}
__device__ __forceinline__ void ffma2(unsigned long long& d,
                                      unsigned long long a,
                                      unsigned long long b) {
    asm("fma.rn.f32x2 %0, %1, %2, %0;" : "+l"(d) : "l"(a), "l"(b));
}
__device__ __forceinline__ void unpack2(unsigned long long v, float& lo, float& hi) {
    unsigned int a, b;
    asm("mov.b64 {%0, %1}, %2;" : "=r"(a), "=r"(b) : "l"(v));
    lo = __uint_as_float(a);
    hi = __uint_as_float(b);
}

// ---------------------------------------------------------------------------
// Main fused kernel.
// Block tile: 128 pairs (16 i x 8 j) x Ntile=128, Ktile=32, 256 threads,
// 8x8 outputs/thread as 8x4 f32x2 accumulators.
// A[m,k] = relu(hx[i(m)][k] + hyb[j(m)][k]) generated per K-tile into smem
// (k-major). W2t streamed from L2 into k-major smem tile. After the K loop,
// relu(.+b2) and fold with W3 into per-m partials; n-tiles loop in-block;
// final cross-tx shuffle reduction writes out[i][j].
// ---------------------------------------------------------------------------
#define MI 16
#define MJ 8
#define MT 128
#define NT 128
#define KT 32

__global__ __launch_bounds__(256, 2)
void critic_main(const float* __restrict__ b2,
                 const float* __restrict__ W3,
                 const float* __restrict__ b3p,
                 float* __restrict__ out) {
    __shared__ float As[KT][MT];   // k-major A tile
    __shared__ float Ws[KT][NT];   // k-major W2 tile

    const int t = threadIdx.x;
    const int tx = t & 15;   // n direction (16)
    const int ty = t >> 4;   // m direction (16): this thread's i_local == ty
    const int i0 = blockIdx.y * MI;
    const int j0 = blockIdx.x * MJ;

    float pm[8];             // per-m partial of final dot (8 j's of row i0+ty)
#pragma unroll
    for (int q = 0; q < 8; q++) pm[q] = 0.f;

    // A-fill thread mapping: kk = t/8, m-range = 16*(t&7) .. +15
    const int fill_kk = t >> 3;
    const int fill_g = t & 7;

    // W-fill thread mapping: c4 = t&31 (float4 col), kk base = t/32
    const int wc4 = t & 31;
    const int wkk = t >> 5;

    for (int n0 = 0; n0 < H; n0 += NT) {
        unsigned long long acc[8][4];
#pragma unroll
        for (int a = 0; a < 8; a++)
#pragma unroll
            for (int p = 0; p < 4; p++) acc[a][p] = 0ull;

        for (int k0 = 0; k0 < H; k0 += KT) {
            __syncthreads();
            // ---- generate A tile: As[kk][m] = relu(hx[i][k] + hyb[j][k])
            {
                const int kc = k0 + fill_kk;
                float hv[8];
#pragma unroll
                for (int jl = 0; jl < 8; jl++)
                    hv[jl] = g_hyb[(j0 + jl) * H + kc];
#pragma unroll
                for (int rep = 0; rep < 2; rep++) {
                    const int il = 2 * fill_g + rep;
                    const float xv = g_hx[(i0 + il) * H + kc];
                    float tmp[8];
#pragma unroll
                    for (int jl = 0; jl < 8; jl++)
                        tmp[jl] = fmaxf(xv + hv[jl], 0.f);
                    *(float4*)&As[fill_kk][il * 8] =
                        make_float4(tmp[0], tmp[1], tmp[2], tmp[3]);
                    *(float4*)&As[fill_kk][il * 8 + 4] =
                        make_float4(tmp[4], tmp[5], tmp[6], tmp[7]);
                }
            }
            // ---- load W tile (k-major, coalesced, conflict-free)
            {
#pragma unroll
                for (int p = 0; p < 4; p++) {
                    const int kk = wkk + p * 8;
                    float4 v = *(const float4*)&g_W2t[(k0 + kk) * H + n0 + wc4 * 4];
                    *(float4*)&Ws[kk][wc4 * 4] = v;
                }
            }
            __syncthreads();
            // ---- compute: 8x8 per thread via f32x2 packed FMA
#pragma unroll
            for (int kk = 0; kk < KT; kk++) {
                float4 a0 = *(const float4*)&As[kk][ty * 8];
                float4 a1 = *(const float4*)&As[kk][ty * 8 + 4];
                ulonglong2 wA = *(const ulonglong2*)&Ws[kk][tx * 8];
                ulonglong2 wB = *(const ulonglong2*)&Ws[kk][tx * 8 + 4];
                unsigned long long wp[4] = {wA.x, wA.y, wB.x, wB.y};
                float av[8] = {a0.x, a0.y, a0.z, a0.w, a1.x, a1.y, a1.z, a1.w};
#pragma unroll
                for (int mm = 0; mm < 8; mm++) {
                    unsigned long long av2 = pack2(av[mm]);
#pragma unroll
                    for (int p = 0; p < 4; p++)
                        ffma2(acc[mm][p], av2, wp[p]);
                }
            }
        }
        // ---- epilogue for this n-tile: relu(.+b2) then fold with W3
#pragma unroll
        for (int p = 0; p < 4; p++) {
            const int n = n0 + tx * 8 + 2 * p;
            const float b2lo = b2[n], b2hi = b2[n + 1];
            const float w3lo = W3[n], w3hi = W3[n + 1];
#pragma unroll
            for (int mm = 0; mm < 8; mm++) {
                float clo, chi;
                unpack2(acc[mm][p], clo, chi);
                clo = fmaxf(clo + b2lo, 0.f);
                chi = fmaxf(chi + b2hi, 0.f);
                pm[mm] = fmaf(clo, w3lo, pm[mm]);
                pm[mm] = fmaf(chi, w3hi, pm[mm]);
            }
        }
    }

    // ---- reduce partials across the 16 tx lanes (same ty within 16-lane group)
#pragma unroll
    for (int mm = 0; mm < 8; mm++) {
        float v = pm[mm];
        v += __shfl_down_sync(0xffffffffu, v, 8, 16);
        v += __shfl_down_sync(0xffffffffu, v, 4, 16);
        v += __shfl_down_sync(0xffffffffu, v, 2, 16);
        v += __shfl_down_sync(0xffffffffu, v, 1, 16);
        pm[mm] = v;
    }
    if (tx == 0) {
        const float b3 = b3p[0];
        float4 o0 = make_float4(pm[0] + b3, pm[1] + b3, pm[2] + b3, pm[3] + b3);
        float4 o1 = make_float4(pm[4] + b3, pm[5] + b3, pm[6] + b3, pm[7] + b3);
        float* dst = &out[(i0 + ty) * B + j0];
        *(float4*)dst = o0;
        *(float4*)(dst + 4) = o1;
    }
}

// ---------------------------------------------------------------------------
extern "C" void kernel_launch(void* const* d_in, const int* in_sizes, int n_in,
                              void* d_out, int out_size) {
    const float* x  = (const float*)d_in[0];
    const float* y  = (const float*)d_in[1];
    const float* W1 = (const float*)d_in[2];
    const float* b1 = (const float*)d_in[3];
    const float* W2 = (const float*)d_in[4];
    const float* b2 = (const float*)d_in[5];
    const float* W3 = (const float*)d_in[6];
    const float* b3 = (const float*)d_in[7];
    float* out = (float*)d_out;

    dim3 gblk(16, 16);
    dim3 ggrd(H / 16, B / 16);
    gemm_h_kernel<<<ggrd, gblk>>>(x, W1, b1, 0, 0);    // -> g_hx
    gemm_h_kernel<<<ggrd, gblk>>>(y, W1, b1, DX, 1);   // -> g_hyb (+b1)
    transpose_kernel<<<dim3(H / 32, H / 32), dim3(32, 8)>>>(W2);
    critic_main<<<dim3(B / MJ, B / MI), 256>>>(b2, W3, b3, out);
}

// round 4
// speedup vs baseline: 2.0653x; 2.0653x over previous
#include <cuda_runtime.h>
#include <cuda_fp16.h>
#include <cstdint>

#define B 512
#define DX 128
#define H 512

// ---------------- scratch (no allocs allowed) ----------------
__device__ float g_hx[B * H];
__device__ float g_hyb[B * H];
__device__ __half g_W2hi[H * H];
__device__ __half g_W2lo[H * H];

// ---------------------------------------------------------------------------
// Layer 1: out[r][h] = sum_d in[r][d] * W1[h][off+d] (+ b1[h] if addb)
// ---------------------------------------------------------------------------
__global__ void gemm_h_kernel(const float* __restrict__ in,
                              const float* __restrict__ W1,
                              const float* __restrict__ b1,
                              int off, int addb) {
    __shared__ float xs[16][17];
    __shared__ float ws[16][17];
    int tx = threadIdx.x, ty = threadIdx.y;
    int r0 = blockIdx.y * 16, h0 = blockIdx.x * 16;
    float acc = 0.f;
    for (int kt = 0; kt < DX; kt += 16) {
        xs[ty][tx] = in[(r0 + ty) * DX + kt + tx];
        ws[ty][tx] = W1[(h0 + ty) * (2 * DX) + off + kt + tx];
        __syncthreads();
#pragma unroll
        for (int k = 0; k < 16; k++)
            acc = fmaf(xs[ty][k], ws[tx][k], acc);
        __syncthreads();
    }
    float bv = addb ? b1[h0 + tx] : 0.f;
    float* outp = addb ? g_hyb : g_hx;
    outp[(r0 + ty) * H + h0 + tx] = acc + bv;
}

// ---------------------------------------------------------------------------
// Split W2 (fp32 [n][k]) into fp16 hi/lo pair, same row-major layout.
// ---------------------------------------------------------------------------
__global__ void wsplit_kernel(const float* __restrict__ W2) {
    int idx = blockIdx.x * 256 + threadIdx.x;
    float w = W2[idx];
    __half hi = __float2half_rn(w);
    float res = w - __half2float(hi);
    g_W2hi[idx] = hi;
    g_W2lo[idx] = __float2half_rn(res);
}

// ---------------------------------------------------------------------------
// helpers
// ---------------------------------------------------------------------------
__device__ __forceinline__ uint32_t smem_u32(const void* p) {
    uint32_t a;
    asm("{ .reg .u64 t; cvta.to.shared.u64 t, %1; cvt.u32.u64 %0, t; }"
        : "=r"(a) : "l"(p));
    return a;
}
__device__ __forceinline__ void ldm_x4(uint32_t& r0, uint32_t& r1,
                                       uint32_t& r2, uint32_t& r3, uint32_t a) {
    asm volatile("ldmatrix.sync.aligned.m8n8.x4.shared.b16 {%0,%1,%2,%3}, [%4];"
                 : "=r"(r0), "=r"(r1), "=r"(r2), "=r"(r3) : "r"(a));
}
__device__ __forceinline__ void mma16816(float* c, uint32_t a0, uint32_t a1,
                                         uint32_t a2, uint32_t a3,
                                         uint32_t b0, uint32_t b1) {
    asm volatile(
        "mma.sync.aligned.m16n8k16.row.col.f32.f16.f16.f32 "
        "{%0,%1,%2,%3}, {%4,%5,%6,%7}, {%8,%9}, {%0,%1,%2,%3};"
        : "+f"(c[0]), "+f"(c[1]), "+f"(c[2]), "+f"(c[3])
        : "r"(a0), "r"(a1), "r"(a2), "r"(a3), "r"(b0), "r"(b1));
}

// ---------------------------------------------------------------------------
// Main fused kernel (Ampere-style HMMA, 2-pass fp16 hi/lo on W).
// CTA: 128 m-rows (8 i x 16 j) x 128 n-tile (loop x4), K chunks of 64.
// 8 warps as 2(m) x 4(n); warp tile 64x32; acc = 4x4 mma tiles x 4 fp32.
// A[m,k] = fp16(relu(hx+hyb)) generated in smem per K-chunk; W hi/lo tiles
// streamed from L2. Epilogue folds relu(D+b2).W3 per n-tile into pm[8],
// reduced via shfl + smem. Everything deterministic.
// ---------------------------------------------------------------------------
#define SM_A   0          // 128 x 64 half = 16KB (SW128-swizzled rows)
#define SM_WH  16384      // 16KB
#define SM_WL  32768      // 16KB
#define SM_BW  49152      // float2[512] = 4KB
#define SM_RED 53248      // float[4][128] = 2KB
#define SMEM_TOTAL 55296

__global__ __launch_bounds__(256, 2)
void critic_hmma(const float* __restrict__ b2,
                 const float* __restrict__ W3,
                 const float* __restrict__ b3p,
                 float* __restrict__ out) {
    extern __shared__ char smem[];
    const uint32_t sb = smem_u32(smem);
    const int t = threadIdx.x;
    const int lane = t & 31;
    const int w = t >> 5;
    const int mw = w & 1;        // m-warp: 0..1 (64 rows each)
    const int nw = w >> 1;       // n-warp: 0..3 (32 cols each)
    const int g = lane >> 2;     // mma row group
    const int t4 = lane & 3;
    const int i0 = blockIdx.y * 8;
    const int j0 = blockIdx.x * 16;

    // preload {b2, W3} pairs
    for (int q = t; q < 512; q += 256)
        *(float2*)(smem + SM_BW + q * 8) = make_float2(b2[q], W3[q]);

    // gen-phase mapping: each thread -> row m=t>>1, half hs=t&1 (32 halves)
    const int gm = t >> 1, ghs = t & 1;
    const int g_il = gm >> 4, g_jl = gm & 15;
    const uint32_t gswz = (uint32_t)((gm & 7) << 4);

    // ldmatrix A lane mapping
    const int a_row_l = lane & 15;
    const int a_kh = lane >> 4;
    uint32_t a_base[4], a_cs[4];
#pragma unroll
    for (int tm = 0; tm < 4; tm++) {
        int row = mw * 64 + tm * 16 + a_row_l;
        a_base[tm] = sb + SM_A + row * 128;
        a_cs[tm] = (uint32_t)((row & 7) << 4) ^ (uint32_t)(a_kh * 16);
    }
    // ldmatrix B lane mapping (x4 covers 16 n x 16 k)
    const int b_n_l = ((lane >> 4) << 3) + (lane & 7);
    const int b_kh = (lane >> 3) & 1;
    uint32_t b_off[2], b_cs[2];
#pragma unroll
    for (int p = 0; p < 2; p++) {
        int n = nw * 32 + p * 16 + b_n_l;
        b_off[p] = (uint32_t)(n * 128);
        b_cs[p] = (uint32_t)((n & 7) << 4) ^ (uint32_t)(b_kh * 16);
    }

    float pm[8];
#pragma unroll
    for (int q = 0; q < 8; q++) pm[q] = 0.f;

    for (int nt = 0; nt < 4; nt++) {
        float acc[4][4][4];
#pragma unroll
        for (int a = 0; a < 4; a++)
#pragma unroll
            for (int b = 0; b < 4; b++)
#pragma unroll
                for (int c = 0; c < 4; c++) acc[a][b][c] = 0.f;

        for (int kc = 0; kc < 8; kc++) {
            __syncthreads();
            // ---- generate A chunk: fp16(relu(hx+hyb)), swizzled
            {
                const float* hxp = &g_hx[(i0 + g_il) * H + kc * 64 + ghs * 32];
                const float* hyp = &g_hyb[(j0 + g_jl) * H + kc * 64 + ghs * 32];
#pragma unroll
                for (int e = 0; e < 4; e++) {
                    float4 x0 = *(const float4*)(hxp + e * 8);
                    float4 x1 = *(const float4*)(hxp + e * 8 + 4);
                    float4 y0 = *(const float4*)(hyp + e * 8);
                    float4 y1 = *(const float4*)(hyp + e * 8 + 4);
                    __half2 h0 = __float22half2_rn(make_float2(
                        fmaxf(x0.x + y0.x, 0.f), fmaxf(x0.y + y0.y, 0.f)));
                    __half2 h1 = __float22half2_rn(make_float2(
                        fmaxf(x0.z + y0.z, 0.f), fmaxf(x0.w + y0.w, 0.f)));
                    __half2 h2 = __float22half2_rn(make_float2(
                        fmaxf(x1.x + y1.x, 0.f), fmaxf(x1.y + y1.y, 0.f)));
                    __half2 h3 = __float22half2_rn(make_float2(
                        fmaxf(x1.z + y1.z, 0.f), fmaxf(x1.w + y1.w, 0.f)));
                    uint32_t soff =
                        (uint32_t)(gm * 128) + (((uint32_t)(ghs * 64 + e * 16)) ^ gswz);
                    *(uint4*)(smem + SM_A + soff) =
                        make_uint4(*(uint32_t*)&h0, *(uint32_t*)&h1,
                                   *(uint32_t*)&h2, *(uint32_t*)&h3);
                }
            }
            // ---- load W hi/lo tiles: rows [nt*128,+128), cols [kc*64,+64)
            {
                const int nrow = t >> 1, hs = t & 1;
                const uint32_t wswz = (uint32_t)((nrow & 7) << 4);
                const __half* srcH = &g_W2hi[(nt * 128 + nrow) * H + kc * 64 + hs * 32];
                const __half* srcL = &g_W2lo[(nt * 128 + nrow) * H + kc * 64 + hs * 32];
#pragma unroll
                for (int e = 0; e < 4; e++) {
                    uint4 vh = *(const uint4*)(srcH + e * 8);
                    uint4 vl = *(const uint4*)(srcL + e * 8);
                    uint32_t soff =
                        (uint32_t)(nrow * 128) + (((uint32_t)(hs * 64 + e * 16)) ^ wswz);
                    *(uint4*)(smem + SM_WH + soff) = vh;
                    *(uint4*)(smem + SM_WL + soff) = vl;
                }
            }
            __syncthreads();
            // ---- compute 4 k16 steps
#pragma unroll
            for (int ks = 0; ks < 4; ks++) {
                uint32_t af[4][4];
#pragma unroll
                for (int tm = 0; tm < 4; tm++)
                    ldm_x4(af[tm][0], af[tm][1], af[tm][2], af[tm][3],
                           a_base[tm] + ((uint32_t)(ks * 32) ^ a_cs[tm]));
                uint32_t bh[2][4], bl[2][4];
#pragma unroll
                for (int p = 0; p < 2; p++) {
                    uint32_t ko = (uint32_t)(ks * 32) ^ b_cs[p];
                    ldm_x4(bh[p][0], bh[p][1], bh[p][2], bh[p][3],
                           sb + SM_WH + b_off[p] + ko);
                    ldm_x4(bl[p][0], bl[p][1], bl[p][2], bl[p][3],
                           sb + SM_WL + b_off[p] + ko);
                }
#pragma unroll
                for (int tm = 0; tm < 4; tm++)
#pragma unroll
                    for (int tn = 0; tn < 4; tn++) {
                        mma16816(acc[tm][tn], af[tm][0], af[tm][1], af[tm][2],
                                 af[tm][3], bh[tn >> 1][(tn & 1) * 2],
                                 bh[tn >> 1][(tn & 1) * 2 + 1]);
                        mma16816(acc[tm][tn], af[tm][0], af[tm][1], af[tm][2],
                                 af[tm][3], bl[tn >> 1][(tn & 1) * 2],
                                 bl[tn >> 1][(tn & 1) * 2 + 1]);
                    }
            }
        }
        // ---- fold this n-tile: relu(D + b2) . W3 into pm
#pragma unroll
        for (int tm = 0; tm < 4; tm++)
#pragma unroll
            for (int tn = 0; tn < 4; tn++) {
                int n_g = nt * 128 + nw * 32 + tn * 8 + 2 * t4;
                float2 bw0 = *(const float2*)(smem + SM_BW + n_g * 8);
                float2 bw1 = *(const float2*)(smem + SM_BW + (n_g + 1) * 8);
                pm[tm * 2] = fmaf(fmaxf(acc[tm][tn][0] + bw0.x, 0.f), bw0.y,
                                  pm[tm * 2]);
                pm[tm * 2] = fmaf(fmaxf(acc[tm][tn][1] + bw1.x, 0.f), bw1.y,
                                  pm[tm * 2]);
                pm[tm * 2 + 1] = fmaf(fmaxf(acc[tm][tn][2] + bw0.x, 0.f), bw0.y,
                                      pm[tm * 2 + 1]);
                pm[tm * 2 + 1] = fmaf(fmaxf(acc[tm][tn][3] + bw1.x, 0.f), bw1.y,
                                      pm[tm * 2 + 1]);
            }
    }

    // ---- reduce pm across the 4 lanes of each row group
#pragma unroll
    for (int q = 0; q < 8; q++) {
        pm[q] += __shfl_xor_sync(0xffffffffu, pm[q], 1);
        pm[q] += __shfl_xor_sync(0xffffffffu, pm[q], 2);
    }
    __syncthreads();
    if (t4 == 0) {
        float* red = (float*)(smem + SM_RED);
#pragma unroll
        for (int tm = 0; tm < 4; tm++) {
            red[nw * 128 + mw * 64 + tm * 16 + g] = pm[tm * 2];
            red[nw * 128 + mw * 64 + tm * 16 + 8 + g] = pm[tm * 2 + 1];
        }
    }
    __syncthreads();
    if (t < 128) {
        const float* red = (const float*)(smem + SM_RED);
        float s = red[t] + red[128 + t] + red[256 + t] + red[384 + t] + b3p[0];
        out[(i0 + (t >> 4)) * B + j0 + (t & 15)] = s;
    }
}

// ---------------------------------------------------------------------------
extern "C" void kernel_launch(void* const* d_in, const int* in_sizes, int n_in,
                              void* d_out, int out_size) {
    const float* x  = (const float*)d_in[0];
    const float* y  = (const float*)d_in[1];
    const float* W1 = (const float*)d_in[2];
    const float* b1 = (const float*)d_in[3];
    const float* W2 = (const float*)d_in[4];
    const float* b2 = (const float*)d_in[5];
    const float* W3 = (const float*)d_in[6];
    const float* b3 = (const float*)d_in[7];
    float* out = (float*)d_out;

    cudaFuncSetAttribute(critic_hmma, cudaFuncAttributeMaxDynamicSharedMemorySize,
                         SMEM_TOTAL);

    dim3 gblk(16, 16);
    dim3 ggrd(H / 16, B / 16);
    gemm_h_kernel<<<ggrd, gblk>>>(x, W1, b1, 0, 0);    // -> g_hx
    gemm_h_kernel<<<ggrd, gblk>>>(y, W1, b1, DX, 1);   // -> g_hyb (+b1)
    wsplit_kernel<<<H * H / 256, 256>>>(W2);           // -> g_W2hi / g_W2lo

    critic_hmma<<<dim3(B / 16, B / 8), 256, SMEM_TOTAL>>>(b2, W3, b3, out);
}

// round 5
// speedup vs baseline: 5.6383x; 2.7300x over previous
#include <cuda_runtime.h>
#include <cuda_fp16.h>
#include <cstdint>

#define B 512
#define DX 128
#define H 512

// ---------------- scratch (no allocs allowed) ----------------
__device__ float g_hx[B * H];
__device__ float g_hyb[B * H];
__device__ __half g_W2h[H * H];

// ---------------------------------------------------------------------------
// Layer 1: out[r][h] = sum_d in[r][d] * W1[h][off+d] (+ b1[h] if addb)
// ---------------------------------------------------------------------------
__global__ void gemm_h_kernel(const float* __restrict__ in,
                              const float* __restrict__ W1,
                              const float* __restrict__ b1,
                              int off, int addb) {
    __shared__ float xs[16][17];
    __shared__ float ws[16][17];
    int tx = threadIdx.x, ty = threadIdx.y;
    int r0 = blockIdx.y * 16, h0 = blockIdx.x * 16;
    float acc = 0.f;
    for (int kt = 0; kt < DX; kt += 16) {
        xs[ty][tx] = in[(r0 + ty) * DX + kt + tx];
        ws[ty][tx] = W1[(h0 + ty) * (2 * DX) + off + kt + tx];
        __syncthreads();
#pragma unroll
        for (int k = 0; k < 16; k++)
            acc = fmaf(xs[ty][k], ws[tx][k], acc);
        __syncthreads();
    }
    float bv = addb ? b1[h0 + tx] : 0.f;
    float* outp = addb ? g_hyb : g_hx;
    outp[(r0 + ty) * H + h0 + tx] = acc + bv;
}

// ---------------------------------------------------------------------------
// Convert W2 fp32 -> fp16 (single copy)
// ---------------------------------------------------------------------------
__global__ void wconv_kernel(const float* __restrict__ W2) {
    int idx = blockIdx.x * 256 + threadIdx.x;
    g_W2h[idx] = __float2half_rn(W2[idx]);
}

// ---------------------------------------------------------------------------
// helpers
// ---------------------------------------------------------------------------
__device__ __forceinline__ uint32_t smem_u32(const void* p) {
    uint32_t a;
    asm("{ .reg .u64 t; cvta.to.shared.u64 t, %1; cvt.u32.u64 %0, t; }"
        : "=r"(a) : "l"(p));
    return a;
}
__device__ __forceinline__ void ldm_x4(uint32_t& r0, uint32_t& r1,
                                       uint32_t& r2, uint32_t& r3, uint32_t a) {
    asm volatile("ldmatrix.sync.aligned.m8n8.x4.shared.b16 {%0,%1,%2,%3}, [%4];"
                 : "=r"(r0), "=r"(r1), "=r"(r2), "=r"(r3) : "r"(a));
}
__device__ __forceinline__ void mma16816(float* c, uint32_t a0, uint32_t a1,
                                         uint32_t a2, uint32_t a3,
                                         uint32_t b0, uint32_t b1) {
    asm volatile(
        "mma.sync.aligned.m16n8k16.row.col.f32.f16.f16.f32 "
        "{%0,%1,%2,%3}, {%4,%5,%6,%7}, {%8,%9}, {%0,%1,%2,%3};"
        : "+f"(c[0]), "+f"(c[1]), "+f"(c[2]), "+f"(c[3])
        : "r"(a0), "r"(a1), "r"(a2), "r"(a3), "r"(b0), "r"(b1));
}
__device__ __forceinline__ void cp16(uint32_t dst, const void* src) {
    asm volatile("cp.async.cg.shared.global [%0], [%1], 16;"
                 :: "r"(dst), "l"(src));
}

// ---------------------------------------------------------------------------
// Main fused kernel, single-pass fp16 HMMA.
// CTA: 256 threads (8 warps = 2 m-warps x 4 n-warps), tile m=128 (8i x 16j).
// Full A [128 x 512] fp16 cached in smem (generated once). N processed in 2
// halves of 256 (acc limit); W tile [256n x 64k] double-buffered via cp.async.
// Warp tile 64m x 64n -> 128 fp32 acc/thread. 16 stages total.
// ---------------------------------------------------------------------------
#define SM_A   0          // 8 chunks x [128 rows x 128B] = 128KB
#define SM_W   131072     // 2 bufs x 32KB
#define SM_BW  196608     // float2[512] = 4KB
#define SM_RED 200704     // float[4][128] = 2KB
#define SMEM_TOTAL 202752

__global__ __launch_bounds__(256, 1)
void critic_hmma(const float* __restrict__ b2,
                 const float* __restrict__ W3,
                 const float* __restrict__ b3p,
                 float* __restrict__ out) {
    extern __shared__ char smem[];
    const uint32_t sb = smem_u32(smem);
    const int t = threadIdx.x;
    const int lane = t & 31;
    const int w = t >> 5;
    const int mw = w & 1;        // m-warp: 0..1 (64 rows each)
    const int nw = w >> 1;       // n-warp: 0..3 (64 cols each)
    const int g = lane >> 2;
    const int t4 = lane & 3;
    const int i0 = blockIdx.y * 8;
    const int j0 = blockIdx.x * 16;

    // preload {b2, W3} pairs
    for (int q = t; q < 512; q += 256)
        *(float2*)(smem + SM_BW + q * 8) = make_float2(b2[q], W3[q]);

    // ---- prologue: generate full A [128m x 512k] fp16 into smem (once)
    // item -> kc = item>>10, row = (item>>3)&127, c16 = item&7  (conflict-free)
    {
#pragma unroll 4
        for (int r = 0; r < 32; ++r) {
            int item = t + r * 256;
            int kc = item >> 10;
            int row = (item >> 3) & 127;
            int c = item & 7;
            int kg = kc * 64 + c * 8;
            const float* hxp = &g_hx[(i0 + (row >> 4)) * H + kg];
            const float* hyp = &g_hyb[(j0 + (row & 15)) * H + kg];
            float4 x0 = *(const float4*)hxp, x1 = *(const float4*)(hxp + 4);
            float4 y0 = *(const float4*)hyp, y1 = *(const float4*)(hyp + 4);
            __half2 h0 = __float22half2_rn(make_float2(
                fmaxf(x0.x + y0.x, 0.f), fmaxf(x0.y + y0.y, 0.f)));
            __half2 h1 = __float22half2_rn(make_float2(
                fmaxf(x0.z + y0.z, 0.f), fmaxf(x0.w + y0.w, 0.f)));
            __half2 h2 = __float22half2_rn(make_float2(
                fmaxf(x1.x + y1.x, 0.f), fmaxf(x1.y + y1.y, 0.f)));
            __half2 h3 = __float22half2_rn(make_float2(
                fmaxf(x1.z + y1.z, 0.f), fmaxf(x1.w + y1.w, 0.f)));
            uint32_t off = (uint32_t)(kc * 16384 + row * 128) +
                           (((uint32_t)(c * 16)) ^ ((uint32_t)((row & 7) << 4)));
            *(uint4*)(smem + SM_A + off) =
                make_uint4(*(uint32_t*)&h0, *(uint32_t*)&h1,
                           *(uint32_t*)&h2, *(uint32_t*)&h3);
        }
    }

    // W producer mapping: item -> n = item>>3 (0..255), c16 = item&7
    auto produceW = [&](int nt, int kc, int buf) {
#pragma unroll
        for (int r = 0; r < 8; ++r) {
            int item = t + r * 256;
            int n = item >> 3;
            int c = item & 7;
            const __half* src = &g_W2h[(nt * 256 + n) * H + kc * 64 + c * 8];
            uint32_t off = (uint32_t)(buf * 32768 + n * 128) +
                           (((uint32_t)(c * 16)) ^ ((uint32_t)((n & 7) << 4)));
            cp16(sb + SM_W + off, src);
        }
        asm volatile("cp.async.commit_group;" ::: "memory");
    };

    // ldmatrix A lane mapping
    const int a_row_l = lane & 15;
    const int a_kh = lane >> 4;
    uint32_t a_base[4], a_cs[4];
#pragma unroll
    for (int tm = 0; tm < 4; tm++) {
        int row = mw * 64 + tm * 16 + a_row_l;
        a_base[tm] = sb + SM_A + row * 128;
        a_cs[tm] = (uint32_t)((row & 7) << 4) ^ (uint32_t)(a_kh * 16);
    }
    // ldmatrix B lane mapping (x4 covers 16 n x 16 k); p = 0..3 -> 64 n
    const int b_n_l = ((lane >> 4) << 3) + (lane & 7);
    const int b_kh = (lane >> 3) & 1;
    uint32_t b_off[4], b_cs[4];
#pragma unroll
    for (int p = 0; p < 4; p++) {
        int n = nw * 64 + p * 16 + b_n_l;
        b_off[p] = (uint32_t)(n * 128);
        b_cs[p] = (uint32_t)((n & 7) << 4) ^ (uint32_t)(b_kh * 16);
    }

    float pm[8];
#pragma unroll
    for (int q = 0; q < 8; q++) pm[q] = 0.f;

    float acc[4][8][4];
#pragma unroll
    for (int a = 0; a < 4; a++)
#pragma unroll
        for (int b = 0; b < 8; b++)
#pragma unroll
            for (int c = 0; c < 4; c++) acc[a][b][c] = 0.f;

    produceW(0, 0, 0);

    for (int s = 0; s < 16; ++s) {
        const int nt = s >> 3, kc = s & 7, buf = s & 1;
        asm volatile("cp.async.wait_group 0;" ::: "memory");
        __syncthreads();
        if (s + 1 < 16) produceW((s + 1) >> 3, (s + 1) & 7, buf ^ 1);

        const uint32_t akc = (uint32_t)(kc * 16384);
        const uint32_t wbase = sb + SM_W + (uint32_t)(buf * 32768);
#pragma unroll
        for (int ks = 0; ks < 4; ks++) {
            uint32_t af[4][4];
#pragma unroll
            for (int tm = 0; tm < 4; tm++)
                ldm_x4(af[tm][0], af[tm][1], af[tm][2], af[tm][3],
                       a_base[tm] + akc + ((uint32_t)(ks * 32) ^ a_cs[tm]));
            uint32_t bf[4][4];
#pragma unroll
            for (int p = 0; p < 4; p++)
                ldm_x4(bf[p][0], bf[p][1], bf[p][2], bf[p][3],
                       wbase + b_off[p] + ((uint32_t)(ks * 32) ^ b_cs[p]));
#pragma unroll
            for (int tm = 0; tm < 4; tm++)
#pragma unroll
                for (int tn = 0; tn < 8; tn++)
                    mma16816(acc[tm][tn], af[tm][0], af[tm][1], af[tm][2],
                             af[tm][3], bf[tn >> 1][(tn & 1) * 2],
                             bf[tn >> 1][(tn & 1) * 2 + 1]);
        }

        if (kc == 7) {
            // ---- fold this 256-n half: relu(D + b2) . W3 into pm
#pragma unroll
            for (int tm = 0; tm < 4; tm++)
#pragma unroll
                for (int tn = 0; tn < 8; tn++) {
                    int n_g = nt * 256 + nw * 64 + tn * 8 + 2 * t4;
                    float2 bw0 = *(const float2*)(smem + SM_BW + n_g * 8);
                    float2 bw1 = *(const float2*)(smem + SM_BW + (n_g + 1) * 8);
                    pm[tm * 2] = fmaf(fmaxf(acc[tm][tn][0] + bw0.x, 0.f), bw0.y,
                                      pm[tm * 2]);
                    pm[tm * 2] = fmaf(fmaxf(acc[tm][tn][1] + bw1.x, 0.f), bw1.y,
                                      pm[tm * 2]);
                    pm[tm * 2 + 1] = fmaf(fmaxf(acc[tm][tn][2] + bw0.x, 0.f),
                                          bw0.y, pm[tm * 2 + 1]);
                    pm[tm * 2 + 1] = fmaf(fmaxf(acc[tm][tn][3] + bw1.x, 0.f),
                                          bw1.y, pm[tm * 2 + 1]);
                    acc[tm][tn][0] = 0.f;
                    acc[tm][tn][1] = 0.f;
                    acc[tm][tn][2] = 0.f;
                    acc[tm][tn][3] = 0.f;
                }
        }
    }

    // ---- reduce pm across the 4 lanes of each row group
#pragma unroll
    for (int q = 0; q < 8; q++) {
        pm[q] += __shfl_xor_sync(0xffffffffu, pm[q], 1);
        pm[q] += __shfl_xor_sync(0xffffffffu, pm[q], 2);
    }
    __syncthreads();
    if (t4 == 0) {
        float* red = (float*)(smem + SM_RED);
#pragma unroll
        for (int tm = 0; tm < 4; tm++) {
            red[nw * 128 + mw * 64 + tm * 16 + g] = pm[tm * 2];
            red[nw * 128 + mw * 64 + tm * 16 + 8 + g] = pm[tm * 2 + 1];
        }
    }
    __syncthreads();
    if (t < 128) {
        const float* red = (const float*)(smem + SM_RED);
        float s = red[t] + red[128 + t] + red[256 + t] + red[384 + t] + b3p[0];
        out[(i0 + (t >> 4)) * B + j0 + (t & 15)] = s;
    }
}

// ---------------------------------------------------------------------------
extern "C" void kernel_launch(void* const* d_in, const int* in_sizes, int n_in,
                              void* d_out, int out_size) {
    const float* x  = (const float*)d_in[0];
    const float* y  = (const float*)d_in[1];
    const float* W1 = (const float*)d_in[2];
    const float* b1 = (const float*)d_in[3];
    const float* W2 = (const float*)d_in[4];
    const float* b2 = (const float*)d_in[5];
    const float* W3 = (const float*)d_in[6];
    const float* b3 = (const float*)d_in[7];
    float* out = (float*)d_out;

    cudaFuncSetAttribute(critic_hmma, cudaFuncAttributeMaxDynamicSharedMemorySize,
                         SMEM_TOTAL);

    dim3 gblk(16, 16);
    dim3 ggrd(H / 16, B / 16);
    gemm_h_kernel<<<ggrd, gblk>>>(x, W1, b1, 0, 0);    // -> g_hx
    gemm_h_kernel<<<ggrd, gblk>>>(y, W1, b1, DX, 1);   // -> g_hyb (+b1)
    wconv_kernel<<<H * H / 256, 256>>>(W2);            // -> g_W2h

    critic_hmma<<<dim3(B / 16, B / 8), 256, SMEM_TOTAL>>>(b2, W3, b3, out);
}

// round 6
// speedup vs baseline: 6.0482x; 1.0727x over previous
#include <cuda_runtime.h>
#include <cuda_fp16.h>
#include <cstdint>

#define B 512
#define DX 128
#define H 512

// ---------------- scratch (no allocs allowed) ----------------
__device__ float g_hx[B * H];
__device__ float g_hyb[B * H];
__device__ __half g_W2h[H * H];

// ---------------------------------------------------------------------------
// Layer 1: out[r][h] = sum_d in[r][d] * W1[h][off+d] (+ b1[h] if addb)
// ---------------------------------------------------------------------------
__global__ void gemm_h_kernel(const float* __restrict__ in,
                              const float* __restrict__ W1,
                              const float* __restrict__ b1,
                              int off, int addb) {
    __shared__ float xs[16][17];
    __shared__ float ws[16][17];
    int tx = threadIdx.x, ty = threadIdx.y;
    int r0 = blockIdx.y * 16, h0 = blockIdx.x * 16;
    float acc = 0.f;
    for (int kt = 0; kt < DX; kt += 16) {
        xs[ty][tx] = in[(r0 + ty) * DX + kt + tx];
        ws[ty][tx] = W1[(h0 + ty) * (2 * DX) + off + kt + tx];
        __syncthreads();
#pragma unroll
        for (int k = 0; k < 16; k++)
            acc = fmaf(xs[ty][k], ws[tx][k], acc);
        __syncthreads();
    }
    float bv = addb ? b1[h0 + tx] : 0.f;
    float* outp = addb ? g_hyb : g_hx;
    outp[(r0 + ty) * H + h0 + tx] = acc + bv;
}

// ---------------------------------------------------------------------------
// Convert W2 fp32 -> fp16 (single copy)
// ---------------------------------------------------------------------------
__global__ void wconv_kernel(const float* __restrict__ W2) {
    int idx = blockIdx.x * 256 + threadIdx.x;
    g_W2h[idx] = __float2half_rn(W2[idx]);
}

// ---------------------------------------------------------------------------
// helpers
// ---------------------------------------------------------------------------
__device__ __forceinline__ uint32_t smem_u32(const void* p) {
    uint32_t a;
    asm("{ .reg .u64 t; cvta.to.shared.u64 t, %1; cvt.u32.u64 %0, t; }"
        : "=r"(a) : "l"(p));
    return a;
}
__device__ __forceinline__ void ldm_x4(uint32_t& r0, uint32_t& r1,
                                       uint32_t& r2, uint32_t& r3, uint32_t a) {
    asm volatile("ldmatrix.sync.aligned.m8n8.x4.shared.b16 {%0,%1,%2,%3}, [%4];"
                 : "=r"(r0), "=r"(r1), "=r"(r2), "=r"(r3) : "r"(a));
}
__device__ __forceinline__ void mma16816(float* c, uint32_t a0, uint32_t a1,
                                         uint32_t a2, uint32_t a3,
                                         uint32_t b0, uint32_t b1) {
    asm volatile(
        "mma.sync.aligned.m16n8k16.row.col.f32.f16.f16.f32 "
        "{%0,%1,%2,%3}, {%4,%5,%6,%7}, {%8,%9}, {%0,%1,%2,%3};"
        : "+f"(c[0]), "+f"(c[1]), "+f"(c[2]), "+f"(c[3])
        : "r"(a0), "r"(a1), "r"(a2), "r"(a3), "r"(b0), "r"(b1));
}
__device__ __forceinline__ void cp16(uint32_t dst, const void* src) {
    asm volatile("cp.async.cg.shared.global [%0], [%1], 16;"
                 :: "r"(dst), "l"(src));
}

// ---------------------------------------------------------------------------
// Main fused kernel, single-pass fp16 HMMA.
// CTA: 512 threads (16 warps = 4 m-warps x 4 n-warps), tile m=128 (8i x 16j).
// Full A [128 x 512] fp16 cached in smem (generated once). N processed in 2
// halves of 256; W tile [256n x 64k] double-buffered via cp.async.
// Warp tile 32m x 64n -> 64 fp32 acc/thread (fits 128 regs @ 512 thr).
// 16 stages; 4 warps/SMSP hide LDSM latency behind sibling MMA streams.
// ---------------------------------------------------------------------------
#define SM_A   0          // 8 chunks x [128 rows x 128B] = 128KB
#define SM_W   131072     // 2 bufs x 32KB
#define SM_BW  196608     // float2[512] = 4KB
#define SM_RED 200704     // float[4][128] = 2KB
#define SMEM_TOTAL 202752

__global__ __launch_bounds__(512, 1)
void critic_hmma(const float* __restrict__ b2,
                 const float* __restrict__ W3,
                 const float* __restrict__ b3p,
                 float* __restrict__ out) {
    extern __shared__ char smem[];
    const uint32_t sb = smem_u32(smem);
    const int t = threadIdx.x;
    const int lane = t & 31;
    const int w = t >> 5;
    const int mw = w & 3;        // m-warp: 0..3 (32 rows each)
    const int nw = w >> 2;       // n-warp: 0..3 (64 cols each)
    const int g = lane >> 2;
    const int t4 = lane & 3;
    const int i0 = blockIdx.y * 8;
    const int j0 = blockIdx.x * 16;

    // preload {b2, W3} pairs
    for (int q = t; q < 512; q += 512)
        *(float2*)(smem + SM_BW + q * 8) = make_float2(b2[q], W3[q]);

    // ---- prologue: generate full A [128m x 512k] fp16 into smem (once)
    {
#pragma unroll 4
        for (int r = 0; r < 16; ++r) {
            int item = t + r * 512;
            int kc = item >> 10;
            int row = (item >> 3) & 127;
            int c = item & 7;
            int kg = kc * 64 + c * 8;
            const float* hxp = &g_hx[(i0 + (row >> 4)) * H + kg];
            const float* hyp = &g_hyb[(j0 + (row & 15)) * H + kg];
            float4 x0 = *(const float4*)hxp, x1 = *(const float4*)(hxp + 4);
            float4 y0 = *(const float4*)hyp, y1 = *(const float4*)(hyp + 4);
            __half2 h0 = __float22half2_rn(make_float2(
                fmaxf(x0.x + y0.x, 0.f), fmaxf(x0.y + y0.y, 0.f)));
            __half2 h1 = __float22half2_rn(make_float2(
                fmaxf(x0.z + y0.z, 0.f), fmaxf(x0.w + y0.w, 0.f)));
            __half2 h2 = __float22half2_rn(make_float2(
                fmaxf(x1.x + y1.x, 0.f), fmaxf(x1.y + y1.y, 0.f)));
            __half2 h3 = __float22half2_rn(make_float2(
                fmaxf(x1.z + y1.z, 0.f), fmaxf(x1.w + y1.w, 0.f)));
            uint32_t off = (uint32_t)(kc * 16384 + row * 128) +
                           (((uint32_t)(c * 16)) ^ ((uint32_t)((row & 7) << 4)));
            *(uint4*)(smem + SM_A + off) =
                make_uint4(*(uint32_t*)&h0, *(uint32_t*)&h1,
                           *(uint32_t*)&h2, *(uint32_t*)&h3);
        }
    }

    // W producer mapping: item -> n = item>>3 (0..255), c16 = item&7
    auto produceW = [&](int nt, int kc, int buf) {
#pragma unroll
        for (int r = 0; r < 4; ++r) {
            int item = t + r * 512;
            int n = item >> 3;
            int c = item & 7;
            const __half* src = &g_W2h[(nt * 256 + n) * H + kc * 64 + c * 8];
            uint32_t off = (uint32_t)(buf * 32768 + n * 128) +
                           (((uint32_t)(c * 16)) ^ ((uint32_t)((n & 7) << 4)));
            cp16(sb + SM_W + off, src);
        }
        asm volatile("cp.async.commit_group;" ::: "memory");
    };

    // ldmatrix A lane mapping (warp covers rows mw*32 .. +32)
    const int a_row_l = lane & 15;
    const int a_kh = lane >> 4;
    uint32_t a_base[2], a_cs[2];
#pragma unroll
    for (int tm = 0; tm < 2; tm++) {
        int row = mw * 32 + tm * 16 + a_row_l;
        a_base[tm] = sb + SM_A + row * 128;
        a_cs[tm] = (uint32_t)((row & 7) << 4) ^ (uint32_t)(a_kh * 16);
    }
    // ldmatrix B lane mapping (x4 covers 16 n x 16 k); p = 0..3 -> 64 n
    const int b_n_l = ((lane >> 4) << 3) + (lane & 7);
    const int b_kh = (lane >> 3) & 1;
    uint32_t b_off[4], b_cs[4];
#pragma unroll
    for (int p = 0; p < 4; p++) {
        int n = nw * 64 + p * 16 + b_n_l;
        b_off[p] = (uint32_t)(n * 128);
        b_cs[p] = (uint32_t)((n & 7) << 4) ^ (uint32_t)(b_kh * 16);
    }

    float pm[4];
#pragma unroll
    for (int q = 0; q < 4; q++) pm[q] = 0.f;

    float acc[2][8][4];
#pragma unroll
    for (int a = 0; a < 2; a++)
#pragma unroll
        for (int b = 0; b < 8; b++)
#pragma unroll
            for (int c = 0; c < 4; c++) acc[a][b][c] = 0.f;

    produceW(0, 0, 0);

    for (int s = 0; s < 16; ++s) {
        const int nt = s >> 3, kc = s & 7, buf = s & 1;
        asm volatile("cp.async.wait_group 0;" ::: "memory");
        __syncthreads();
        if (s + 1 < 16) produceW((s + 1) >> 3, (s + 1) & 7, buf ^ 1);

        const uint32_t akc = (uint32_t)(kc * 16384);
        const uint32_t wbase = sb + SM_W + (uint32_t)(buf * 32768);
#pragma unroll
        for (int ks = 0; ks < 4; ks++) {
            uint32_t af[2][4];
#pragma unroll
            for (int tm = 0; tm < 2; tm++)
                ldm_x4(af[tm][0], af[tm][1], af[tm][2], af[tm][3],
                       a_base[tm] + akc + ((uint32_t)(ks * 32) ^ a_cs[tm]));
            uint32_t bf[4][4];
#pragma unroll
            for (int p = 0; p < 4; p++)
                ldm_x4(bf[p][0], bf[p][1], bf[p][2], bf[p][3],
                       wbase + b_off[p] + ((uint32_t)(ks * 32) ^ b_cs[p]));
#pragma unroll
            for (int tm = 0; tm < 2; tm++)
#pragma unroll
                for (int tn = 0; tn < 8; tn++)
                    mma16816(acc[tm][tn], af[tm][0], af[tm][1], af[tm][2],
                             af[tm][3], bf[tn >> 1][(tn & 1) * 2],
                             bf[tn >> 1][(tn & 1) * 2 + 1]);
        }

        if (kc == 7) {
            // ---- fold this 256-n half: relu(D + b2) . W3 into pm
#pragma unroll
            for (int tm = 0; tm < 2; tm++)
#pragma unroll
                for (int tn = 0; tn < 8; tn++) {
                    int n_g = nt * 256 + nw * 64 + tn * 8 + 2 * t4;
                    float2 bw0 = *(const float2*)(smem + SM_BW + n_g * 8);
                    float2 bw1 = *(const float2*)(smem + SM_BW + (n_g + 1) * 8);
                    pm[tm * 2] = fmaf(fmaxf(acc[tm][tn][0] + bw0.x, 0.f), bw0.y,
                                      pm[tm * 2]);
                    pm[tm * 2] = fmaf(fmaxf(acc[tm][tn][1] + bw1.x, 0.f), bw1.y,
                                      pm[tm * 2]);
                    pm[tm * 2 + 1] = fmaf(fmaxf(acc[tm][tn][2] + bw0.x, 0.f),
                                          bw0.y, pm[tm * 2 + 1]);
                    pm[tm * 2 + 1] = fmaf(fmaxf(acc[tm][tn][3] + bw1.x, 0.f),
                                          bw1.y, pm[tm * 2 + 1]);
                    acc[tm][tn][0] = 0.f;
                    acc[tm][tn][1] = 0.f;
                    acc[tm][tn][2] = 0.f;
                    acc[tm][tn][3] = 0.f;
                }
        }
    }

    // ---- reduce pm across the 4 lanes of each row group
#pragma unroll
    for (int q = 0; q < 4; q++) {
        pm[q] += __shfl_xor_sync(0xffffffffu, pm[q], 1);
        pm[q] += __shfl_xor_sync(0xffffffffu, pm[q], 2);
    }
    __syncthreads();
    if (t4 == 0) {
        float* red = (float*)(smem + SM_RED);
#pragma unroll
        for (int tm = 0; tm < 2; tm++) {
            red[nw * 128 + mw * 32 + tm * 16 + g] = pm[tm * 2];
            red[nw * 128 + mw * 32 + tm * 16 + 8 + g] = pm[tm * 2 + 1];
        }
    }
    __syncthreads();
    if (t < 128) {
        const float* red = (const float*)(smem + SM_RED);
        float s = red[t] + red[128 + t] + red[256 + t] + red[384 + t] + b3p[0];
        out[(i0 + (t >> 4)) * B + j0 + (t & 15)] = s;
    }
}

// ---------------------------------------------------------------------------
extern "C" void kernel_launch(void* const* d_in, const int* in_sizes, int n_in,
                              void* d_out, int out_size) {
    const float* x  = (const float*)d_in[0];
    const float* y  = (const float*)d_in[1];
    const float* W1 = (const float*)d_in[2];
    const float* b1 = (const float*)d_in[3];
    const float* W2 = (const float*)d_in[4];
    const float* b2 = (const float*)d_in[5];
    const float* W3 = (const float*)d_in[6];
    const float* b3 = (const float*)d_in[7];
    float* out = (float*)d_out;

    cudaFuncSetAttribute(critic_hmma, cudaFuncAttributeMaxDynamicSharedMemorySize,
                         SMEM_TOTAL);

    dim3 gblk(16, 16);
    dim3 ggrd(H / 16, B / 16);
    gemm_h_kernel<<<ggrd, gblk>>>(x, W1, b1, 0, 0);    // -> g_hx
    gemm_h_kernel<<<ggrd, gblk>>>(y, W1, b1, DX, 1);   // -> g_hyb (+b1)
    wconv_kernel<<<H * H / 256, 256>>>(W2);            // -> g_W2h

    critic_hmma<<<dim3(B / 16, B / 8), 512, SMEM_TOTAL>>>(b2, W3, b3, out);
}